// round 13
// baseline (speedup 1.0000x reference)
#include <cuda_runtime.h>

#define L_CHK 16                     // chunk length along T
#define MAX_CPL 16                   // max chunks per lane in warp-scan pass2
#define SCRATCH_CAP_V4 (1 << 20)     // float4 count -> 16 MB each
#define MAX_D (1 << 20)

// Scratch, pair-packed: float4 [c][q] = (re0,im0,re1,im1) for channels 2q,2q+1.
// float2 view at [c*D + d] is layout-identical.
__device__ float4 g_carry4 [SCRATCH_CAP_V4];
__device__ float4 g_prefix4[SCRATCH_CAP_V4];
// Per-channel decay tables: z = exp(-exp(size)+i*theta), zL = z^L_CHK.
__device__ float2 g_z [MAX_D];
__device__ float2 g_zL[MAX_D];

// ===========================================================================
// Pass 0: precompute per-channel z and z^L (hoists expf/sincosf out of the
// bandwidth kernels; tables live in L2).
// ===========================================================================
__global__ void __launch_bounds__(256) dln_zprep(
    const float* __restrict__ sz, const float* __restrict__ th, int D)
{
    const int d = blockIdx.x * blockDim.x + threadIdx.x;
    if (d >= D) return;
    const float e = expf(sz[d]);
    const float r = expf(-e);
    float si, co; sincosf(th[d], &si, &co);
    g_z[d] = make_float2(r * co, r * si);
    const float rL = expf(-(float)L_CHK * e);          // underflow->0 ok
    float siL, coL; sincosf((float)L_CHK * th[d], &siL, &coL);
    g_zL[d] = make_float2(rL * coL, rL * siL);
}

// ===========================================================================
// Pass 1 (vector, D%4==0): 4 channels/thread, float4 x loads.
// Grid ((D/4+255)/256, C) -> (D/4)*C threads (262144 at D=2048, C=512).
// ===========================================================================
__global__ void __launch_bounds__(256) dln_pass1_v4(
    const float* __restrict__ x, int D, int T, int C)
{
    const int P4 = D >> 2, P2 = D >> 1;
    const int p  = blockIdx.x * blockDim.x + threadIdx.x;
    const int c  = blockIdx.y;
    if (p >= P4 || c >= C) return;

    const int t0  = c * L_CHK;
    const int len = (T - t0 < L_CHK) ? (T - t0) : L_CHK;

    const float4 za = ((const float4*)g_z)[2 * p];      // (zr0,zi0,zr1,zi1)
    const float4 zb = ((const float4*)g_z)[2 * p + 1];  // (zr2,zi2,zr3,zi3)
    const float zr[4] = {za.x, za.z, zb.x, zb.z};
    const float zi[4] = {za.y, za.w, zb.y, zb.w};

    const float4* xp = (const float4*)(x + (long long)t0 * D) + p;

    float vr[4] = {0.f, 0.f, 0.f, 0.f}, vi[4] = {0.f, 0.f, 0.f, 0.f};
    if (len == L_CHK) {
#pragma unroll
        for (int t = 0; t < L_CHK; ++t) {
            const float4 xv = xp[t * P4];
            const float xa[4] = {xv.x, xv.y, xv.z, xv.w};
#pragma unroll
            for (int k = 0; k < 4; ++k) {
                const float nvr = fmaf(zr[k], vr[k], fmaf(-zi[k], vi[k], xa[k]));
                const float nvi = fmaf(zi[k], vr[k], zr[k] * vi[k]);
                vr[k] = nvr; vi[k] = nvi;
            }
        }
    } else {
        for (int t = 0; t < len; ++t) {
            const float4 xv = xp[t * P4];
            const float xa[4] = {xv.x, xv.y, xv.z, xv.w};
#pragma unroll
            for (int k = 0; k < 4; ++k) {
                const float nvr = fmaf(zr[k], vr[k], fmaf(-zi[k], vi[k], xa[k]));
                const float nvi = fmaf(zi[k], vr[k], zr[k] * vi[k]);
                vr[k] = nvr; vi[k] = nvi;
            }
        }
    }
    const long long base = (long long)c * P2 + 2 * p;
    g_carry4[base]     = make_float4(vr[0], vi[0], vr[1], vi[1]);
    g_carry4[base + 1] = make_float4(vr[2], vi[2], vr[3], vi[3]);
}

// ===========================================================================
// Pass 2 (warp-per-channel Kogge-Stone scan over chunk carries; zL from table).
// ===========================================================================
__global__ void __launch_bounds__(256) dln_pass2_w(int D, int C, int cpl)
{
    const float2* carry2  = (const float2*)g_carry4;
    float2*       prefix2 = (float2*)g_prefix4;

    const int gtid = blockIdx.x * blockDim.x + threadIdx.x;
    const int d    = gtid >> 5;
    const int lane = gtid & 31;
    if (d >= D) return;

    const float2 zL = g_zL[d];
    const float zr = zL.x, zi = zL.y;

    float cr[MAX_CPL], ci[MAX_CPL];
#pragma unroll
    for (int i = 0; i < MAX_CPL; ++i) {
        if (i < cpl) {
            const int c = lane * cpl + i;
            if (c < C) {
                const float2 cv = carry2[(long long)c * D + d];
                cr[i] = cv.x; ci[i] = cv.y;
            } else { cr[i] = 0.f; ci[i] = 0.f; }
        }
    }

    float Pr = 1.f, Pi = 0.f, Vr = 0.f, Vi = 0.f;
#pragma unroll
    for (int i = 0; i < MAX_CPL; ++i) {
        if (i < cpl && lane * cpl + i < C) {
            const float nVr = fmaf(Vr, zr, fmaf(-Vi, zi, cr[i]));
            const float nVi = fmaf(Vr, zi, fmaf(Vi, zr, ci[i]));
            const float nPr = Pr * zr - Pi * zi;
            const float nPi = Pr * zi + Pi * zr;
            Vr = nVr; Vi = nVi; Pr = nPr; Pi = nPi;
        }
    }

#pragma unroll
    for (int k = 1; k < 32; k <<= 1) {
        const float aPr = __shfl_up_sync(0xffffffffu, Pr, k);
        const float aPi = __shfl_up_sync(0xffffffffu, Pi, k);
        const float aVr = __shfl_up_sync(0xffffffffu, Vr, k);
        const float aVi = __shfl_up_sync(0xffffffffu, Vi, k);
        if (lane >= k) {
            const float tVr = fmaf(aVr, Pr, fmaf(-aVi, Pi, Vr));
            const float tVi = fmaf(aVr, Pi, fmaf(aVi, Pr, Vi));
            const float tPr = aPr * Pr - aPi * Pi;
            const float tPi = aPr * Pi + aPi * Pr;
            Vr = tVr; Vi = tVi; Pr = tPr; Pi = tPi;
        }
    }

    float Rr = __shfl_up_sync(0xffffffffu, Vr, 1);
    float Ri = __shfl_up_sync(0xffffffffu, Vi, 1);
    if (lane == 0) { Rr = 0.f; Ri = 0.f; }

#pragma unroll
    for (int i = 0; i < MAX_CPL; ++i) {
        if (i < cpl) {
            const int c = lane * cpl + i;
            if (c < C) {
                prefix2[(long long)c * D + d] = make_float2(Rr, Ri);
                const float nRr = fmaf(Rr, zr, fmaf(-Ri, zi, cr[i]));
                const float nRi = fmaf(Rr, zi, fmaf(Ri, zr, ci[i]));
                Rr = nRr; Ri = nRi;
            }
        }
    }
}

// ===========================================================================
// Pass 3 (vector, REAL output): 4 channels/thread, float4 loads + float4
// streaming stores of real parts.
// ===========================================================================
__global__ void __launch_bounds__(256) dln_pass3_real_v4(
    const float* __restrict__ x, float* __restrict__ out,
    int D, int T, int C, long long out_cap_floats)
{
    const int P4 = D >> 2, P2 = D >> 1;
    const int p  = blockIdx.x * blockDim.x + threadIdx.x;
    const int c  = blockIdx.y;
    if (p >= P4 || c >= C) return;

    const int t0  = c * L_CHK;
    const int len = (T - t0 < L_CHK) ? (T - t0) : L_CHK;

    const float4 za = ((const float4*)g_z)[2 * p];
    const float4 zb = ((const float4*)g_z)[2 * p + 1];
    const float zr[4] = {za.x, za.z, zb.x, zb.z};
    const float zi[4] = {za.y, za.w, zb.y, zb.w};

    const long long base = (long long)c * P2 + 2 * p;
    const float4 a = g_prefix4[base];
    const float4 b = g_prefix4[base + 1];
    float vr[4] = {a.x, a.z, b.x, b.z};
    float vi[4] = {a.y, a.w, b.y, b.w};

    const float4* xp = (const float4*)(x + (long long)t0 * D) + p;

    if (len == L_CHK && (long long)(t0 + L_CHK) * D <= out_cap_floats) {
        float4* op = (float4*)(out + (long long)t0 * D) + p;
#pragma unroll
        for (int t = 0; t < L_CHK; ++t) {
            const float4 xv = xp[t * P4];
            const float xa[4] = {xv.x, xv.y, xv.z, xv.w};
#pragma unroll
            for (int k = 0; k < 4; ++k) {
                const float nvr = fmaf(zr[k], vr[k], fmaf(-zi[k], vi[k], xa[k]));
                const float nvi = fmaf(zi[k], vr[k], zr[k] * vi[k]);
                vr[k] = nvr; vi[k] = nvi;
            }
            __stcs(op + t * P4, make_float4(vr[0], vr[1], vr[2], vr[3]));
        }
    } else {
        for (int t = 0; t < len; ++t) {
            const float4 xv = xp[t * P4];
            const float xa[4] = {xv.x, xv.y, xv.z, xv.w};
#pragma unroll
            for (int k = 0; k < 4; ++k) {
                const float nvr = fmaf(zr[k], vr[k], fmaf(-zi[k], vi[k], xa[k]));
                const float nvi = fmaf(zi[k], vr[k], zr[k] * vi[k]);
                vr[k] = nvr; vi[k] = nvi;
            }
            const long long row = (long long)(t0 + t) * D + 4 * p;
#pragma unroll
            for (int k = 0; k < 4; ++k)
                if (row + k < out_cap_floats) __stcs(out + row + k, vr[k]);
        }
    }
}

// ===========================================================================
// Scalar fallbacks (any D / interleaved mode) — float2 scratch view [c*D+d].
// ===========================================================================
__global__ void __launch_bounds__(256) dln_pass1_s(
    const float* __restrict__ x, int D, int T, int C)
{
    float2* carry = (float2*)g_carry4;
    const int d = blockIdx.x * blockDim.x + threadIdx.x;
    const int c = blockIdx.y;
    if (d >= D || c >= C) return;
    const int t0  = c * L_CHK;
    const int len = (T - t0 < L_CHK) ? (T - t0) : L_CHK;
    const float2 z = g_z[d];
    const float zr = z.x, zi = z.y;
    const float* xp = x + (long long)t0 * D + d;
    float vr = 0.f, vi = 0.f;
    for (int t = 0; t < len; ++t) {
        const float xv = xp[(long long)t * D];
        const float nvr = fmaf(zr, vr, fmaf(-zi, vi, xv));
        const float nvi = fmaf(zi, vr, zr * vi);
        vr = nvr; vi = nvi;
    }
    carry[(long long)c * D + d] = make_float2(vr, vi);
}

__global__ void __launch_bounds__(256) dln_pass2_s(int D, int C)
{
    float2* carry  = (float2*)g_carry4;
    float2* prefix = (float2*)g_prefix4;
    const int d = blockIdx.x * blockDim.x + threadIdx.x;
    if (d >= D) return;
    const float2 zL = g_zL[d];
    const float zLr = zL.x, zLi = zL.y;
    float vr = 0.f, vi = 0.f;
    for (int c = 0; c < C; ++c) {
        const long long idx = (long long)c * D + d;
        prefix[idx] = make_float2(vr, vi);
        const float2 cv = carry[idx];
        const float nvr = fmaf(zLr, vr, fmaf(-zLi, vi, cv.x));
        const float nvi = fmaf(zLi, vr, fmaf(zLr, vi, cv.y));
        vr = nvr; vi = nvi;
    }
}

__global__ void __launch_bounds__(256) dln_pass3_real_s(
    const float* __restrict__ x, float* __restrict__ out,
    int D, int T, int C, long long out_cap_floats)
{
    float2* prefix = (float2*)g_prefix4;
    const int d = blockIdx.x * blockDim.x + threadIdx.x;
    const int c = blockIdx.y;
    if (d >= D || c >= C) return;
    const int t0  = c * L_CHK;
    const int len = (T - t0 < L_CHK) ? (T - t0) : L_CHK;
    const float2 z = g_z[d];
    const float zr = z.x, zi = z.y;
    const float2 v0 = prefix[(long long)c * D + d];
    float vr = v0.x, vi = v0.y;
    const float* xp = x + (long long)t0 * D + d;
    for (int t = 0; t < len; ++t) {
        const float xv = xp[(long long)t * D];
        const float nvr = fmaf(zr, vr, fmaf(-zi, vi, xv));
        const float nvi = fmaf(zi, vr, zr * vi);
        vr = nvr; vi = nvi;
        const long long lidx = (long long)(t0 + t) * D + d;
        if (lidx < out_cap_floats) __stcs(out + lidx, vr);
    }
}

__global__ void __launch_bounds__(256) dln_pass3_cplx_s(
    const float* __restrict__ x, float* __restrict__ out,
    int D, int T, int C, long long out_cap_floats)
{
    float2* prefix = (float2*)g_prefix4;
    const int d = blockIdx.x * blockDim.x + threadIdx.x;
    const int c = blockIdx.y;
    if (d >= D || c >= C) return;
    const int t0  = c * L_CHK;
    const int len = (T - t0 < L_CHK) ? (T - t0) : L_CHK;
    const float2 z = g_z[d];
    const float zr = z.x, zi = z.y;
    const float2 v0 = prefix[(long long)c * D + d];
    float vr = v0.x, vi = v0.y;
    const float* xp = x + (long long)t0 * D + d;
    for (int t = 0; t < len; ++t) {
        const float xv = xp[(long long)t * D];
        const float nvr = fmaf(zr, vr, fmaf(-zi, vi, xv));
        const float nvi = fmaf(zi, vr, zr * vi);
        vr = nvr; vi = nvi;
        const long long o = 2 * ((long long)(t0 + t) * D + d);
        if (o + 1 < out_cap_floats) { __stcs(out + o, vr); __stcs(out + o + 1, vi); }
    }
}

extern "C" void kernel_launch(void* const* d_in, const int* in_sizes, int n_in,
                              void* d_out, int out_size)
{
    if (n_in < 3) return;

    int xi = 0;
    for (int i = 1; i < n_in; ++i)
        if (in_sizes[i] > in_sizes[xi]) xi = i;

    const float* x = (const float*)d_in[xi];
    const float* sv[2] = {nullptr, nullptr};
    long long    ss[2] = {0, 0};
    int ns = 0;
    for (int i = 0; i < n_in && ns < 2; ++i)
        if (i != xi) { sv[ns] = (const float*)d_in[i]; ss[ns] = in_sizes[i]; ++ns; }
    if (ns < 2) return;
    const float* sz = sv[0];
    const float* th = sv[1];

    const long long big   = in_sizes[xi];
    const long long small = ss[0] < ss[1] ? ss[0] : ss[1];
    if (small <= 0 || big <= 0 || big % small) return;

    const long long T = big / small;                 // unit-invariant
    if (T <= 0 || T > (1 << 20)) return;

    const long long osz = out_size;
    long long D = 0;
    int interleaved = 0;
    if (osz % T == 0 && (osz / T == small || 4 * (osz / T) == small)) {
        D = osz / T;  interleaved = 0;               // f32 real [T,D]
    } else if (osz % (2 * T) == 0 &&
               (osz / (2 * T) == small || 4 * (osz / (2 * T)) == small)) {
        D = osz / (2 * T);  interleaved = 1;         // interleaved complex
    } else return;
    if (D <= 0 || D > MAX_D) return;

    const int C   = (int)((T + L_CHK - 1) / L_CHK);
    const int cpl = (C + 31) / 32;
    if ((long long)C * D > 2LL * SCRATCH_CAP_V4) return;   // float2 capacity

    dim3 blk(256);
    dln_zprep<<<(unsigned)((D + 255) / 256), blk>>>(sz, th, (int)D);

    if (!interleaved && (D & 3) == 0 && cpl <= MAX_CPL) {
        const int P4 = (int)(D >> 2);
        dim3 g1((P4 + 255) / 256, (unsigned)C);
        dln_pass1_v4<<<g1, blk>>>(x, (int)D, (int)T, C);
        dln_pass2_w<<<(unsigned)(((long long)D * 32 + 255) / 256), blk>>>(
            (int)D, C, cpl);
        dln_pass3_real_v4<<<g1, blk>>>(x, (float*)d_out,
                                       (int)D, (int)T, C, osz);
    } else {
        dim3 gA((unsigned)((D + 255) / 256), (unsigned)C);
        dln_pass1_s<<<gA, blk>>>(x, (int)D, (int)T, C);
        if (cpl <= MAX_CPL)
            dln_pass2_w<<<(unsigned)(((long long)D * 32 + 255) / 256), blk>>>(
                (int)D, C, cpl);
        else
            dln_pass2_s<<<(unsigned)((D + 255) / 256), blk>>>((int)D, C);
        if (interleaved)
            dln_pass3_cplx_s<<<gA, blk>>>(x, (float*)d_out,
                                          (int)D, (int)T, C, osz);
        else
            dln_pass3_real_s<<<gA, blk>>>(x, (float*)d_out,
                                          (int)D, (int)T, C, osz);
    }
}